// round 2
// baseline (speedup 1.0000x reference)
#include <cuda_runtime.h>
#include <math.h>

// Problem constants
#define S_   2048
#define L_   2048
#define T_   4096   // L_ + S_
#define HID_ 2048
#define NH_  16
#define KVH_ 8
#define HD_  128
#define GRP_ 2

// ---------------- scratch (device globals; no allocation allowed) ----------
__device__ float g_Q[(size_t)S_ * HID_];          // Q proj, natural [s][h*HD+d]
__device__ float g_Ktmp[(size_t)S_ * KVH_ * HD_]; // K proj from hidden (pre-norm)
__device__ float g_Qr[(size_t)NH_ * S_ * HD_];    // normed+rope'd Q  [h][s][d]
__device__ float g_Kfull[(size_t)KVH_ * T_ * HD_];// [kvh][t][d]  (ctx rows 0..L-1, self rows L..)
__device__ float g_Vfull[(size_t)KVH_ * T_ * HD_];
__device__ float g_attn[(size_t)S_ * NH_ * HD_];  // attention out, natural [s][h*HD+d]

// ---------------- SGEMM:  C[M,N] = A[M,K] * W[N,K]^T  ----------------------
// headStride==0 : natural row-major C (ldc=N)
// headStride!=0 : scatter C[m,n] -> base[(n/128)*headStride + (m+rowOff)*128 + n%128]
#define BM 128
#define BN 128
#define BK 16

__global__ __launch_bounds__(256)
void sgemm_nt(const float* __restrict__ A, const float* __restrict__ W,
              float* __restrict__ C, int M, int N, int K,
              long headStride, int rowOff)
{
    __shared__ float As[BK][BM];
    __shared__ float Ws[BK][BN];

    const int tid = threadIdx.x;
    const int bn  = blockIdx.x;
    const int bm  = blockIdx.y;
    const int tm  = tid >> 4;   // 0..15
    const int tn  = tid & 15;   // 0..15

    const float* Ab = A + (long)bm * BM * K;
    const float* Wb = W + (long)bn * BN * K;

    float acc[8][8];
#pragma unroll
    for (int i = 0; i < 8; i++)
#pragma unroll
        for (int j = 0; j < 8; j++) acc[i][j] = 0.f;

    for (int kt = 0; kt < K; kt += BK) {
#pragma unroll
        for (int it = 0; it < 2; it++) {
            int f  = tid + it * 256;      // 0..511 float4 slots
            int r  = f >> 2;              // row 0..127
            int kq = (f & 3) << 2;        // 0,4,8,12
            float4 va = *(const float4*)(Ab + (long)r * K + kt + kq);
            As[kq + 0][r] = va.x; As[kq + 1][r] = va.y;
            As[kq + 2][r] = va.z; As[kq + 3][r] = va.w;
            float4 vw = *(const float4*)(Wb + (long)r * K + kt + kq);
            Ws[kq + 0][r] = vw.x; Ws[kq + 1][r] = vw.y;
            Ws[kq + 2][r] = vw.z; Ws[kq + 3][r] = vw.w;
        }
        __syncthreads();

#pragma unroll
        for (int kk = 0; kk < BK; kk++) {
            float a[8], b[8];
            *(float4*)(a)     = *(const float4*)&As[kk][tm * 8];
            *(float4*)(a + 4) = *(const float4*)&As[kk][tm * 8 + 4];
            *(float4*)(b)     = *(const float4*)&Ws[kk][tn * 8];
            *(float4*)(b + 4) = *(const float4*)&Ws[kk][tn * 8 + 4];
#pragma unroll
            for (int i = 0; i < 8; i++)
#pragma unroll
                for (int j = 0; j < 8; j++)
                    acc[i][j] = fmaf(a[i], b[j], acc[i][j]);
        }
        __syncthreads();
    }

    if (headStride == 0) {
        float* Cb = C + (long)(bm * BM + tm * 8) * N + bn * BN + tn * 8;
#pragma unroll
        for (int i = 0; i < 8; i++) {
            *(float4*)(Cb + (long)i * N)     = *(float4*)&acc[i][0];
            *(float4*)(Cb + (long)i * N + 4) = *(float4*)&acc[i][4];
        }
    } else {
        // BN == HD_ == 128 -> head index == bn, in-head col == tn*8+j
        float* Cb = C + (long)bn * headStride
                      + (long)(bm * BM + tm * 8 + rowOff) * HD_ + tn * 8;
#pragma unroll
        for (int i = 0; i < 8; i++) {
            *(float4*)(Cb + (long)i * HD_)     = *(float4*)&acc[i][0];
            *(float4*)(Cb + (long)i * HD_ + 4) = *(float4*)&acc[i][4];
        }
    }
}

// ---------------- RMSNorm + RoPE on Q and K ---------------------------------
// grid (S_, NH_+KVH_), 128 threads (one per d)
__global__ __launch_bounds__(128)
void normrope_kernel(const float* __restrict__ qw, const float* __restrict__ kw)
{
    const int s  = blockIdx.x;
    const int hh = blockIdx.y;           // 0..15 => Q head, 16..23 => K head
    const int d  = threadIdx.x;
    const bool isQ = hh < NH_;

    float x;
    if (isQ) x = g_Q[(long)s * HID_ + hh * HD_ + d];
    else     x = g_Ktmp[(long)s * (KVH_ * HD_) + (hh - NH_) * HD_ + d];

    // block reduction of sum(x^2) over 128 threads
    float v = x * x;
#pragma unroll
    for (int off = 16; off > 0; off >>= 1)
        v += __shfl_xor_sync(0xffffffffu, v, off);
    __shared__ float wsum[4];
    const int lane = d & 31, wid = d >> 5;
    if (lane == 0) wsum[wid] = v;
    __syncthreads();
    const float var = (wsum[0] + wsum[1] + wsum[2] + wsum[3]) * (1.0f / HD_);
    const float rinv = rsqrtf(var + 1e-6f);

    const float w = isQ ? qw[d] : kw[d];
    const float y = x * rinv * w;

    __shared__ float yb[HD_];
    yb[d] = y;
    __syncthreads();
    const float yrot = (d < 64) ? -yb[d + 64] : yb[d - 64];

    // position_ids == arange(S) by construction
    const float pos  = (float)s;
    const int   i    = d & 63;
    const float invf = powf(10000.0f, -(float)i * (1.0f / 64.0f));
    const float ang  = pos * invf;
    float cs, sn;
    sincosf(ang, &sn, &cs);

    const float out = y * cs + yrot * sn;

    if (isQ) g_Qr[((long)hh * S_ + s) * HD_ + d] = out;
    else     g_Kfull[((long)(hh - NH_) * T_ + (L_ + s)) * HD_ + d] = out;
}

// ---------------- Flash attention (fp32) ------------------------------------
// grid (S_/64, NH_), 256 threads. smem: Qs[128][64] + Ks[128][64] + Vs[64][128]
// Ps (64 x stride 65) aliases Ks.
#define ABM 64
#define ABN 64
#define PS_STRIDE 65
#define ASMEM ((HD_*ABM + HD_*ABN + ABN*HD_) * 4)

__global__ __launch_bounds__(256)
void attn_kernel()
{
    extern __shared__ float sm[];
    float* Qs = sm;                    // [d][r], stride ABM
    float* Ks = sm + HD_ * ABM;        // [d][c], stride ABN
    float* Vs = sm + 2 * HD_ * ABM;    // [r][d], stride HD_
    float* Ps = Ks;                    // alias: [row][j], stride PS_STRIDE

    const int h   = blockIdx.y;
    const int q0  = blockIdx.x * ABM;
    const int kvh = h / GRP_;
    const int tid = threadIdx.x;
    const int ty  = tid >> 4;          // 0..15 (4 rows each)
    const int tx  = tid & 15;          // 0..15 (4 S-cols / 8 O-cols each)

    const float scale = 0.08838834764831845f;  // 128^-0.5

    const float* Qg = g_Qr   + ((long)h * S_ + q0) * HD_;
    const float* Kg = g_Kfull + (long)kvh * T_ * HD_;
    const float* Vg = g_Vfull + (long)kvh * T_ * HD_;

    // load Q transposed into smem (scaled)
    {
        const int r = tid & 63;
#pragma unroll
        for (int it = 0; it < 8; it++) {
            int c4 = (tid >> 6) + it * 4;          // 0..31
            float4 v = *(const float4*)(Qg + (long)r * HD_ + c4 * 4);
            Qs[(c4 * 4 + 0) * ABM + r] = v.x * scale;
            Qs[(c4 * 4 + 1) * ABM + r] = v.y * scale;
            Qs[(c4 * 4 + 2) * ABM + r] = v.z * scale;
            Qs[(c4 * 4 + 3) * ABM + r] = v.w * scale;
        }
    }

    float m[4], lsum[4], O[4][8];
#pragma unroll
    for (int i = 0; i < 4; i++) {
        m[i] = -INFINITY; lsum[i] = 0.f;
#pragma unroll
        for (int c = 0; c < 8; c++) O[i][c] = 0.f;
    }

    for (int kt = 0; kt < T_; kt += ABN) {
        __syncthreads();   // prev PV done (Ps aliases Ks; Vs reused)

        // K tile transposed
        {
            const int r = tid & 63;
#pragma unroll
            for (int it = 0; it < 8; it++) {
                int c4 = (tid >> 6) + it * 4;
                float4 v = *(const float4*)(Kg + (long)(kt + r) * HD_ + c4 * 4);
                Ks[(c4 * 4 + 0) * ABN + r] = v.x;
                Ks[(c4 * 4 + 1) * ABN + r] = v.y;
                Ks[(c4 * 4 + 2) * ABN + r] = v.z;
                Ks[(c4 * 4 + 3) * ABN + r] = v.w;
            }
        }
        // V tile row-major
#pragma unroll
        for (int it = 0; it < 8; it++) {
            int f = tid + it * 256;
            int r = f >> 5, c4 = f & 31;
            *(float4*)(Vs + (long)r * HD_ + c4 * 4) =
                *(const float4*)(Vg + (long)(kt + r) * HD_ + c4 * 4);
        }
        __syncthreads();

        // S tile: s[i][j] = sum_d Q[4ty+i][d] * K[4tx+j][d]
        float sv[4][4];
#pragma unroll
        for (int i = 0; i < 4; i++)
#pragma unroll
            for (int j = 0; j < 4; j++) sv[i][j] = 0.f;

#pragma unroll 8
        for (int d = 0; d < HD_; d++) {
            float4 q = *(const float4*)(Qs + d * ABM + ty * 4);
            float4 k = *(const float4*)(Ks + d * ABN + tx * 4);
            sv[0][0] = fmaf(q.x, k.x, sv[0][0]); sv[0][1] = fmaf(q.x, k.y, sv[0][1]);
            sv[0][2] = fmaf(q.x, k.z, sv[0][2]); sv[0][3] = fmaf(q.x, k.w, sv[0][3]);
            sv[1][0] = fmaf(q.y, k.x, sv[1][0]); sv[1][1] = fmaf(q.y, k.y, sv[1][1]);
            sv[1][2] = fmaf(q.y, k.z, sv[1][2]); sv[1][3] = fmaf(q.y, k.w, sv[1][3]);
            sv[2][0] = fmaf(q.z, k.x, sv[2][0]); sv[2][1] = fmaf(q.z, k.y, sv[2][1]);
            sv[2][2] = fmaf(q.z, k.z, sv[2][2]); sv[2][3] = fmaf(q.z, k.w, sv[2][3]);
            sv[3][0] = fmaf(q.w, k.x, sv[3][0]); sv[3][1] = fmaf(q.w, k.y, sv[3][1]);
            sv[3][2] = fmaf(q.w, k.z, sv[3][2]); sv[3][3] = fmaf(q.w, k.w, sv[3][3]);
        }

        // online softmax (row reductions across the 16 tx lanes, width-16)
        float p[4][4];
#pragma unroll
        for (int i = 0; i < 4; i++) {
            float mt = fmaxf(fmaxf(sv[i][0], sv[i][1]), fmaxf(sv[i][2], sv[i][3]));
#pragma unroll
            for (int off = 8; off > 0; off >>= 1)
                mt = fmaxf(mt, __shfl_xor_sync(0xffffffffu, mt, off, 16));
            float mnew = fmaxf(m[i], mt);
            float cor  = expf(m[i] - mnew);   // exp(-inf)=0 on first tile
            m[i] = mnew;
            lsum[i] *= cor;
#pragma unroll
            for (int c = 0; c < 8; c++) O[i][c] *= cor;
            float ps = 0.f;
#pragma unroll
            for (int j = 0; j < 4; j++) {
                p[i][j] = expf(sv[i][j] - mnew);
                ps += p[i][j];
            }
#pragma unroll
            for (int off = 8; off > 0; off >>= 1)
                ps += __shfl_xor_sync(0xffffffffu, ps, off, 16);
            lsum[i] += ps;
        }

        __syncthreads();   // all Ks reads done before P store (alias)
#pragma unroll
        for (int i = 0; i < 4; i++)
#pragma unroll
            for (int j = 0; j < 4; j++)
                Ps[(ty * 4 + i) * PS_STRIDE + tx * 4 + j] = p[i][j];
        __syncthreads();

        // O[i][c] += sum_j P[i][j] * V[j][c]   (c = tx*8 .. tx*8+7)
#pragma unroll 4
        for (int j = 0; j < ABN; j++) {
            float4 v0 = *(const float4*)(Vs + (long)j * HD_ + tx * 8);
            float4 v1 = *(const float4*)(Vs + (long)j * HD_ + tx * 8 + 4);
            float p0 = Ps[(ty * 4 + 0) * PS_STRIDE + j];
            float p1 = Ps[(ty * 4 + 1) * PS_STRIDE + j];
            float p2 = Ps[(ty * 4 + 2) * PS_STRIDE + j];
            float p3 = Ps[(ty * 4 + 3) * PS_STRIDE + j];
            O[0][0]=fmaf(p0,v0.x,O[0][0]); O[0][1]=fmaf(p0,v0.y,O[0][1]);
            O[0][2]=fmaf(p0,v0.z,O[0][2]); O[0][3]=fmaf(p0,v0.w,O[0][3]);
            O[0][4]=fmaf(p0,v1.x,O[0][4]); O[0][5]=fmaf(p0,v1.y,O[0][5]);
            O[0][6]=fmaf(p0,v1.z,O[0][6]); O[0][7]=fmaf(p0,v1.w,O[0][7]);
            O[1][0]=fmaf(p1,v0.x,O[1][0]); O[1][1]=fmaf(p1,v0.y,O[1][1]);
            O[1][2]=fmaf(p1,v0.z,O[1][2]); O[1][3]=fmaf(p1,v0.w,O[1][3]);
            O[1][4]=fmaf(p1,v1.x,O[1][4]); O[1][5]=fmaf(p1,v1.y,O[1][5]);
            O[1][6]=fmaf(p1,v1.z,O[1][6]); O[1][7]=fmaf(p1,v1.w,O[1][7]);
            O[2][0]=fmaf(p2,v0.x,O[2][0]); O[2][1]=fmaf(p2,v0.y,O[2][1]);
            O[2][2]=fmaf(p2,v0.z,O[2][2]); O[2][3]=fmaf(p2,v0.w,O[2][3]);
            O[2][4]=fmaf(p2,v1.x,O[2][4]); O[2][5]=fmaf(p2,v1.y,O[2][5]);
            O[2][6]=fmaf(p2,v1.z,O[2][6]); O[2][7]=fmaf(p2,v1.w,O[2][7]);
            O[3][0]=fmaf(p3,v0.x,O[3][0]); O[3][1]=fmaf(p3,v0.y,O[3][1]);
            O[3][2]=fmaf(p3,v0.z,O[3][2]); O[3][3]=fmaf(p3,v0.w,O[3][3]);
            O[3][4]=fmaf(p3,v1.x,O[3][4]); O[3][5]=fmaf(p3,v1.y,O[3][5]);
            O[3][6]=fmaf(p3,v1.z,O[3][6]); O[3][7]=fmaf(p3,v1.w,O[3][7]);
        }
    }

    // epilogue: normalize by lsum, write natural layout [s][h*HD+d]
#pragma unroll
    for (int i = 0; i < 4; i++) {
        const float inv = 1.0f / lsum[i];
        float* op = g_attn + (long)(q0 + ty * 4 + i) * (NH_ * HD_) + h * HD_ + tx * 8;
        float4 o0, o1;
        o0.x = O[i][0]*inv; o0.y = O[i][1]*inv; o0.z = O[i][2]*inv; o0.w = O[i][3]*inv;
        o1.x = O[i][4]*inv; o1.y = O[i][5]*inv; o1.z = O[i][6]*inv; o1.w = O[i][7]*inv;
        *(float4*)op       = o0;
        *(float4*)(op + 4) = o1;
    }
}

// ---------------- launch -----------------------------------------------------
extern "C" void kernel_launch(void* const* d_in, const int* in_sizes, int n_in,
                              void* d_out, int out_size)
{
    const float* hidden  = (const float*)d_in[0];
    const float* context = (const float*)d_in[1];
    // d_in[2] = position_ids (== arange(S), value known; dtype ambiguous -> unused)
    const float* Wq  = (const float*)d_in[3];
    const float* Wk  = (const float*)d_in[4];
    const float* Wv  = (const float*)d_in[5];
    const float* Wo  = (const float*)d_in[6];
    const float* Wkc = (const float*)d_in[7];
    const float* Wvc = (const float*)d_in[8];
    const float* qnw = (const float*)d_in[9];
    const float* knw = (const float*)d_in[10];

    float *Qp, *Ktp, *Kfp, *Vfp, *Ap;
    cudaGetSymbolAddress((void**)&Qp,  g_Q);
    cudaGetSymbolAddress((void**)&Ktp, g_Ktmp);
    cudaGetSymbolAddress((void**)&Kfp, g_Kfull);
    cudaGetSymbolAddress((void**)&Vfp, g_Vfull);
    cudaGetSymbolAddress((void**)&Ap,  g_attn);

    const long hstride = (long)T_ * HD_;

    // projections
    sgemm_nt<<<dim3(HID_ / BN, S_ / BM), 256>>>(hidden,  Wq,  Qp,  S_, HID_,       HID_, 0, 0);
    sgemm_nt<<<dim3(KVH_ * HD_ / BN, S_ / BM), 256>>>(hidden,  Wk,  Ktp, S_, KVH_ * HD_, HID_, 0, 0);
    sgemm_nt<<<dim3(KVH_ * HD_ / BN, S_ / BM), 256>>>(hidden,  Wv,  Vfp, S_, KVH_ * HD_, HID_, hstride, L_);
    sgemm_nt<<<dim3(KVH_ * HD_ / BN, L_ / BM), 256>>>(context, Wkc, Kfp, L_, KVH_ * HD_, HID_, hstride, 0);
    sgemm_nt<<<dim3(KVH_ * HD_ / BN, L_ / BM), 256>>>(context, Wvc, Vfp, L_, KVH_ * HD_, HID_, hstride, 0);

    // rmsnorm + rope (Q heads and K heads)
    normrope_kernel<<<dim3(S_, NH_ + KVH_), 128>>>(qnw, knw);

    // attention
    cudaFuncSetAttribute(attn_kernel, cudaFuncAttributeMaxDynamicSharedMemorySize, ASMEM);
    attn_kernel<<<dim3(S_ / ABM, NH_), 256, ASMEM>>>();

    // output projection -> d_out
    sgemm_nt<<<dim3(HID_ / BN, S_ / BM), 256>>>(Ap, Wo, (float*)d_out, S_, HID_, HID_, 0, 0);
}

// round 4
// speedup vs baseline: 1.3656x; 1.3656x over previous
#include <cuda_runtime.h>
#include <cuda_bf16.h>
#include <math.h>
#include <stdint.h>

// Problem constants
#define S_   2048
#define L_   2048
#define T_   4096   // L_ + S_
#define HID_ 2048
#define NH_  16
#define KVH_ 8
#define HD_  128
#define GRP_ 2

// ===================== scratch (device globals) ==============================
__device__ float g_Q[(size_t)S_ * HID_];
__device__ float g_Ktmp[(size_t)S_ * KVH_ * HD_];
__device__ float g_Qr[(size_t)NH_ * S_ * HD_];
__device__ float g_Kfull[(size_t)KVH_ * T_ * HD_];
__device__ float g_Vfull[(size_t)KVH_ * T_ * HD_];
__device__ float g_attn[(size_t)S_ * NH_ * HD_];

// bf16 hi/lo splits
__device__ __nv_bfloat16 g_hid_hi[(size_t)S_ * HID_],  g_hid_lo[(size_t)S_ * HID_];
__device__ __nv_bfloat16 g_ctx_hi[(size_t)L_ * HID_],  g_ctx_lo[(size_t)L_ * HID_];
__device__ __nv_bfloat16 g_att_hi[(size_t)S_ * HID_],  g_att_lo[(size_t)S_ * HID_];
__device__ __nv_bfloat16 g_wq_hi[(size_t)NH_ * HD_ * HID_], g_wq_lo[(size_t)NH_ * HD_ * HID_];
__device__ __nv_bfloat16 g_wo_hi[(size_t)HID_ * NH_ * HD_], g_wo_lo[(size_t)HID_ * NH_ * HD_];
__device__ __nv_bfloat16 g_wk_hi[(size_t)KVH_ * HD_ * HID_], g_wk_lo[(size_t)KVH_ * HD_ * HID_];
__device__ __nv_bfloat16 g_wv_hi[(size_t)KVH_ * HD_ * HID_], g_wv_lo[(size_t)KVH_ * HD_ * HID_];
__device__ __nv_bfloat16 g_wkc_hi[(size_t)KVH_ * HD_ * HID_], g_wkc_lo[(size_t)KVH_ * HD_ * HID_];
__device__ __nv_bfloat16 g_wvc_hi[(size_t)KVH_ * HD_ * HID_], g_wvc_lo[(size_t)KVH_ * HD_ * HID_];

// ===================== small PTX helpers (baseline sm_80+ ISA only) =========
__device__ __forceinline__ uint32_t smem_u32(const void* p) {
    uint32_t a;
    asm("{ .reg .u64 t; cvta.to.shared.u64 t, %1; cvt.u32.u64 %0, t; }"
        : "=r"(a) : "l"(p));
    return a;
}
__device__ __forceinline__ void cp16(uint32_t s, const void* g) {
    asm volatile("cp.async.cg.shared.global [%0], [%1], 16;" :: "r"(s), "l"(g));
}
__device__ __forceinline__ void cp_commit() {
    asm volatile("cp.async.commit_group;" ::: "memory");
}
template <int N> __device__ __forceinline__ void cp_wait() {
    asm volatile("cp.async.wait_group %0;" :: "n"(N) : "memory");
}
__device__ __forceinline__ void ldsm_x4(uint32_t& r0, uint32_t& r1,
                                        uint32_t& r2, uint32_t& r3, uint32_t addr) {
    asm volatile("ldmatrix.sync.aligned.m8n8.x4.shared.b16 {%0,%1,%2,%3}, [%4];"
                 : "=r"(r0), "=r"(r1), "=r"(r2), "=r"(r3) : "r"(addr));
}
__device__ __forceinline__ void mma16816(float* c, const uint32_t* a, const uint32_t* b) {
    asm volatile(
        "mma.sync.aligned.m16n8k16.row.col.f32.bf16.bf16.f32 "
        "{%0,%1,%2,%3}, {%4,%5,%6,%7}, {%8,%9}, {%0,%1,%2,%3};"
        : "+f"(c[0]), "+f"(c[1]), "+f"(c[2]), "+f"(c[3])
        : "r"(a[0]), "r"(a[1]), "r"(a[2]), "r"(a[3]), "r"(b[0]), "r"(b[1]));
}

// ===================== fp32 -> bf16 hi/lo split ==============================
__global__ __launch_bounds__(256)
void split_bf16(const float4* __restrict__ x, __nv_bfloat162* __restrict__ hi,
                __nv_bfloat162* __restrict__ lo, int n4)
{
    int i = blockIdx.x * 256 + threadIdx.x;
    if (i >= n4) return;
    float4 v = x[i];
    __nv_bfloat16 h0 = __float2bfloat16(v.x);
    __nv_bfloat16 h1 = __float2bfloat16(v.y);
    __nv_bfloat16 h2 = __float2bfloat16(v.z);
    __nv_bfloat16 h3 = __float2bfloat16(v.w);
    __nv_bfloat16 l0 = __float2bfloat16(v.x - __bfloat162float(h0));
    __nv_bfloat16 l1 = __float2bfloat16(v.y - __bfloat162float(h1));
    __nv_bfloat16 l2 = __float2bfloat16(v.z - __bfloat162float(h2));
    __nv_bfloat16 l3 = __float2bfloat16(v.w - __bfloat162float(h3));
    hi[2 * i]     = __nv_bfloat162(h0, h1);
    hi[2 * i + 1] = __nv_bfloat162(h2, h3);
    lo[2 * i]     = __nv_bfloat162(l0, l1);
    lo[2 * i + 1] = __nv_bfloat162(l2, l3);
}

// ===================== HMMA GEMM (bf16x3): C = A * W^T =======================
// A[M,K] row-major, W[N,K] row-major (both K-contiguous) -> mma row.col.
// CTA tile 128x128, BK=32, 8 warps (2x4), warp tile 64x32.
// headStride==0 : C row-major (ldc=N)
// headStride!=0 : C[m,n] -> base[(n/128)*headStride + (m+rowOff)*128 + n%128]
#define GBK        32
#define G_ASTR     40                       // bf16 row stride (80B; conflict-free ldmatrix)
#define G_TILEB    (128 * G_ASTR * 2)       // 10240 B per tile
#define G_BUFB     (4 * G_TILEB)            // Ahi, Alo, Whi, Wlo
#define G_SMEM     (2 * G_BUFB)             // 81920 B

__global__ __launch_bounds__(256)
void gemm_mma(const __nv_bfloat16* __restrict__ Ahi, const __nv_bfloat16* __restrict__ Alo,
              const __nv_bfloat16* __restrict__ Whi, const __nv_bfloat16* __restrict__ Wlo,
              float* __restrict__ C, int K, int N, long headStride, int rowOff)
{
    extern __shared__ char sm[];
    const uint32_t smb = smem_u32(sm);
    const int tid  = threadIdx.x;
    const int lane = tid & 31;
    const int wid  = tid >> 5;
    const int bn = blockIdx.x, bm = blockIdx.y;

    const __nv_bfloat16* srcs[4];
    srcs[0] = Ahi + (long)bm * 128 * K;
    srcs[1] = Alo + (long)bm * 128 * K;
    srcs[2] = Whi + (long)bn * 128 * K;
    srcs[3] = Wlo + (long)bn * 128 * K;

    // per-thread load slots: 8 x 16B per buffer fill
    // f = tid + i*256 ; tile = f>>9 ; rem = f&511 ; row = rem>>2 ; q = rem&3
    auto issue_loads = [&](int kt, int buf) {
#pragma unroll
        for (int i = 0; i < 8; i++) {
            int f = tid + i * 256;
            int tile = f >> 9, rem = f & 511;
            int r = rem >> 2, q = rem & 3;
            uint32_t soff = smb + buf * G_BUFB + tile * G_TILEB + (r * G_ASTR + q * 8) * 2;
            cp16(soff, srcs[tile] + (long)r * K + kt + q * 8);
        }
        cp_commit();
    };

    float acc[4][4][4];
#pragma unroll
    for (int mi = 0; mi < 4; mi++)
#pragma unroll
        for (int nt = 0; nt < 4; nt++)
#pragma unroll
            for (int c = 0; c < 4; c++) acc[mi][nt][c] = 0.f;

    const int wm = (wid >> 2) * 64;       // warp m offset (0,64)
    const int wn = (wid & 3) * 32;        // warp n offset (0..96)
    const int arow  = lane & 15;
    const int acol  = (lane >> 4) * 8;    // 0 or 8
    const int brow  = (lane & 7) + ((lane & 16) ? 8 : 0);
    const int bcol  = (lane & 8) ? 8 : 0;

    const int niter = K / GBK;
    issue_loads(0, 0);

    for (int it = 0; it < niter; it++) {
        const int buf = it & 1;
        if (it + 1 < niter) {
            issue_loads((it + 1) * GBK, buf ^ 1);
            cp_wait<1>();
        } else {
            cp_wait<0>();
        }
        __syncthreads();

        const uint32_t Ah = smb + buf * G_BUFB;
        const uint32_t Al = Ah + G_TILEB;
        const uint32_t Wh = Ah + 2 * G_TILEB;
        const uint32_t Wl = Ah + 3 * G_TILEB;

#pragma unroll
        for (int ks = 0; ks < 2; ks++) {
            uint32_t ah[4][4], al[4][4], bh[4][2], bl[4][2];
#pragma unroll
            for (int mi = 0; mi < 4; mi++) {
                uint32_t off = (uint32_t)((wm + mi * 16 + arow) * G_ASTR + ks * 16 + acol) * 2;
                ldsm_x4(ah[mi][0], ah[mi][1], ah[mi][2], ah[mi][3], Ah + off);
                ldsm_x4(al[mi][0], al[mi][1], al[mi][2], al[mi][3], Al + off);
            }
#pragma unroll
            for (int p = 0; p < 2; p++) {
                uint32_t off = (uint32_t)((wn + p * 16 + brow) * G_ASTR + ks * 16 + bcol) * 2;
                ldsm_x4(bh[2*p][0], bh[2*p][1], bh[2*p+1][0], bh[2*p+1][1], Wh + off);
                ldsm_x4(bl[2*p][0], bl[2*p][1], bl[2*p+1][0], bl[2*p+1][1], Wl + off);
            }
#pragma unroll
            for (int mi = 0; mi < 4; mi++)
#pragma unroll
                for (int nt = 0; nt < 4; nt++) {
                    mma16816(acc[mi][nt], ah[mi], bh[nt]);
                    mma16816(acc[mi][nt], ah[mi], bl[nt]);
                    mma16816(acc[mi][nt], al[mi], bh[nt]);
                }
        }
        __syncthreads();
    }

    // epilogue
    const int g = lane >> 2;      // row within m16
    const int t = lane & 3;       // col pair within n8
#pragma unroll
    for (int mi = 0; mi < 4; mi++) {
#pragma unroll
        for (int nt = 0; nt < 4; nt++) {
            int row = bm * 128 + wm + mi * 16 + g;
            int col = wn + nt * 8 + t * 2;
            float* p0;
            if (headStride == 0) p0 = C + (long)row * N + bn * 128 + col;
            else                 p0 = C + (long)bn * headStride + (long)(row + rowOff) * HD_ + col;
            float2 v0 = make_float2(acc[mi][nt][0], acc[mi][nt][1]);
            float2 v1 = make_float2(acc[mi][nt][2], acc[mi][nt][3]);
            *(float2*)p0 = v0;
            float* p1 = p0 + (headStride == 0 ? (long)8 * N : (long)8 * HD_);
            *(float2*)p1 = v1;
        }
    }
}

// ---------------- RMSNorm + RoPE on Q and K ---------------------------------
__global__ __launch_bounds__(128)
void normrope_kernel(const float* __restrict__ qw, const float* __restrict__ kw)
{
    const int s  = blockIdx.x;
    const int hh = blockIdx.y;           // 0..15 => Q head, 16..23 => K head
    const int d  = threadIdx.x;
    const bool isQ = hh < NH_;

    float x;
    if (isQ) x = g_Q[(long)s * HID_ + hh * HD_ + d];
    else     x = g_Ktmp[(long)s * (KVH_ * HD_) + (hh - NH_) * HD_ + d];

    float v = x * x;
#pragma unroll
    for (int off = 16; off > 0; off >>= 1)
        v += __shfl_xor_sync(0xffffffffu, v, off);
    __shared__ float wsum[4];
    const int lane = d & 31, wid = d >> 5;
    if (lane == 0) wsum[wid] = v;
    __syncthreads();
    const float var = (wsum[0] + wsum[1] + wsum[2] + wsum[3]) * (1.0f / HD_);
    const float rinv = rsqrtf(var + 1e-6f);

    const float w = isQ ? qw[d] : kw[d];
    const float y = x * rinv * w;

    __shared__ float yb[HD_];
    yb[d] = y;
    __syncthreads();
    const float yrot = (d < 64) ? -yb[d + 64] : yb[d - 64];

    const float pos  = (float)s;                   // position_ids == arange(S)
    const int   i    = d & 63;
    const float invf = powf(10000.0f, -(float)i * (1.0f / 64.0f));
    const float ang  = pos * invf;
    float cs, sn;
    sincosf(ang, &sn, &cs);

    const float out = y * cs + yrot * sn;

    if (isQ) g_Qr[((long)hh * S_ + s) * HD_ + d] = out;
    else     g_Kfull[((long)(hh - NH_) * T_ + (L_ + s)) * HD_ + d] = out;
}

// ---------------- Flash attention (fp32 SIMT) --------------------------------
#define ABM 64
#define ABN 64
#define PS_STRIDE 65
#define ASMEM ((HD_*ABM + HD_*ABN + ABN*HD_) * 4)

__global__ __launch_bounds__(256)
void attn_kernel()
{
    extern __shared__ float smf[];
    float* Qs = smf;
    float* Ks = smf + HD_ * ABM;
    float* Vs = smf + 2 * HD_ * ABM;
    float* Ps = Ks;

    const int h   = blockIdx.y;
    const int q0  = blockIdx.x * ABM;
    const int kvh = h / GRP_;
    const int tid = threadIdx.x;
    const int ty  = tid >> 4;
    const int tx  = tid & 15;

    const float scale = 0.08838834764831845f;

    const float* Qg = g_Qr    + ((long)h * S_ + q0) * HD_;
    const float* Kg = g_Kfull + (long)kvh * T_ * HD_;
    const float* Vg = g_Vfull + (long)kvh * T_ * HD_;

    {
        const int r = tid & 63;
#pragma unroll
        for (int it = 0; it < 8; it++) {
            int c4 = (tid >> 6) + it * 4;
            float4 v = *(const float4*)(Qg + (long)r * HD_ + c4 * 4);
            Qs[(c4 * 4 + 0) * ABM + r] = v.x * scale;
            Qs[(c4 * 4 + 1) * ABM + r] = v.y * scale;
            Qs[(c4 * 4 + 2) * ABM + r] = v.z * scale;
            Qs[(c4 * 4 + 3) * ABM + r] = v.w * scale;
        }
    }

    float m[4], lsum[4], O[4][8];
#pragma unroll
    for (int i = 0; i < 4; i++) {
        m[i] = -INFINITY; lsum[i] = 0.f;
#pragma unroll
        for (int c = 0; c < 8; c++) O[i][c] = 0.f;
    }

    for (int kt = 0; kt < T_; kt += ABN) {
        __syncthreads();
        {
            const int r = tid & 63;
#pragma unroll
            for (int it = 0; it < 8; it++) {
                int c4 = (tid >> 6) + it * 4;
                float4 v = *(const float4*)(Kg + (long)(kt + r) * HD_ + c4 * 4);
                Ks[(c4 * 4 + 0) * ABN + r] = v.x;
                Ks[(c4 * 4 + 1) * ABN + r] = v.y;
                Ks[(c4 * 4 + 2) * ABN + r] = v.z;
                Ks[(c4 * 4 + 3) * ABN + r] = v.w;
            }
        }
#pragma unroll
        for (int it = 0; it < 8; it++) {
            int f = tid + it * 256;
            int r = f >> 5, c4 = f & 31;
            *(float4*)(Vs + (long)r * HD_ + c4 * 4) =
                *(const float4*)(Vg + (long)(kt + r) * HD_ + c4 * 4);
        }
        __syncthreads();

        float sv[4][4];
#pragma unroll
        for (int i = 0; i < 4; i++)
#pragma unroll
            for (int j = 0; j < 4; j++) sv[i][j] = 0.f;

#pragma unroll 8
        for (int d = 0; d < HD_; d++) {
            float4 q = *(const float4*)(Qs + d * ABM + ty * 4);
            float4 k = *(const float4*)(Ks + d * ABN + tx * 4);
            sv[0][0] = fmaf(q.x, k.x, sv[0][0]); sv[0][1] = fmaf(q.x, k.y, sv[0][1]);
            sv[0][2] = fmaf(q.x, k.z, sv[0][2]); sv[0][3] = fmaf(q.x, k.w, sv[0][3]);
            sv[1][0] = fmaf(q.y, k.x, sv[1][0]); sv[1][1] = fmaf(q.y, k.y, sv[1][1]);
            sv[1][2] = fmaf(q.y, k.z, sv[1][2]); sv[1][3] = fmaf(q.y, k.w, sv[1][3]);
            sv[2][0] = fmaf(q.z, k.x, sv[2][0]); sv[2][1] = fmaf(q.z, k.y, sv[2][1]);
            sv[2][2] = fmaf(q.z, k.z, sv[2][2]); sv[2][3] = fmaf(q.z, k.w, sv[2][3]);
            sv[3][0] = fmaf(q.w, k.x, sv[3][0]); sv[3][1] = fmaf(q.w, k.y, sv[3][1]);
            sv[3][2] = fmaf(q.w, k.z, sv[3][2]); sv[3][3] = fmaf(q.w, k.w, sv[3][3]);
        }

        float p[4][4];
#pragma unroll
        for (int i = 0; i < 4; i++) {
            float mt = fmaxf(fmaxf(sv[i][0], sv[i][1]), fmaxf(sv[i][2], sv[i][3]));
#pragma unroll
            for (int off = 8; off > 0; off >>= 1)
                mt = fmaxf(mt, __shfl_xor_sync(0xffffffffu, mt, off, 16));
            float mnew = fmaxf(m[i], mt);
            float cor  = (m[i] == -INFINITY) ? 0.f : __expf(m[i] - mnew);
            m[i] = mnew;
            lsum[i] *= cor;
#pragma unroll
            for (int c = 0; c < 8; c++) O[i][c] *= cor;
            float ps = 0.f;
#pragma unroll
            for (int j = 0; j < 4; j++) {
                p[i][j] = __expf(sv[i][j] - mnew);
                ps += p[i][j];
            }
#pragma unroll
            for (int off = 8; off > 0; off >>= 1)
                ps += __shfl_xor_sync(0xffffffffu, ps, off, 16);
            lsum[i] += ps;
        }

        __syncthreads();
#pragma unroll
        for (int i = 0; i < 4; i++)
#pragma unroll
            for (int j = 0; j < 4; j++)
                Ps[(ty * 4 + i) * PS_STRIDE + tx * 4 + j] = p[i][j];
        __syncthreads();

#pragma unroll 4
        for (int j = 0; j < ABN; j++) {
            float4 v0 = *(const float4*)(Vs + (long)j * HD_ + tx * 8);
            float4 v1 = *(const float4*)(Vs + (long)j * HD_ + tx * 8 + 4);
            float p0 = Ps[(ty * 4 + 0) * PS_STRIDE + j];
            float p1 = Ps[(ty * 4 + 1) * PS_STRIDE + j];
            float p2 = Ps[(ty * 4 + 2) * PS_STRIDE + j];
            float p3 = Ps[(ty * 4 + 3) * PS_STRIDE + j];
            O[0][0]=fmaf(p0,v0.x,O[0][0]); O[0][1]=fmaf(p0,v0.y,O[0][1]);
            O[0][2]=fmaf(p0,v0.z,O[0][2]); O[0][3]=fmaf(p0,v0.w,O[0][3]);
            O[0][4]=fmaf(p0,v1.x,O[0][4]); O[0][5]=fmaf(p0,v1.y,O[0][5]);
            O[0][6]=fmaf(p0,v1.z,O[0][6]); O[0][7]=fmaf(p0,v1.w,O[0][7]);
            O[1][0]=fmaf(p1,v0.x,O[1][0]); O[1][1]=fmaf(p1,v0.y,O[1][1]);
            O[1][2]=fmaf(p1,v0.z,O[1][2]); O[1][3]=fmaf(p1,v0.w,O[1][3]);
            O[1][4]=fmaf(p1,v1.x,O[1][4]); O[1][5]=fmaf(p1,v1.y,O[1][5]);
            O[1][6]=fmaf(p1,v1.z,O[1][6]); O[1][7]=fmaf(p1,v1.w,O[1][7]);
            O[2][0]=fmaf(p2,v0.x,O[2][0]); O[2][1]=fmaf(p2,v0.y,O[2][1]);
            O[2][2]=fmaf(p2,v0.z,O[2][2]); O[2][3]=fmaf(p2,v0.w,O[2][3]);
            O[2][4]=fmaf(p2,v1.x,O[2][4]); O[2][5]=fmaf(p2,v1.y,O[2][5]);
            O[2][6]=fmaf(p2,v1.z,O[2][6]); O[2][7]=fmaf(p2,v1.w,O[2][7]);
            O[3][0]=fmaf(p3,v0.x,O[3][0]); O[3][1]=fmaf(p3,v0.y,O[3][1]);
            O[3][2]=fmaf(p3,v0.z,O[3][2]); O[3][3]=fmaf(p3,v0.w,O[3][3]);
            O[3][4]=fmaf(p3,v1.x,O[3][4]); O[3][5]=fmaf(p3,v1.y,O[3][5]);
            O[3][6]=fmaf(p3,v1.z,O[3][6]); O[3][7]=fmaf(p3,v1.w,O[3][7]);
        }
    }

#pragma unroll
    for (int i = 0; i < 4; i++) {
        const float inv = 1.0f / lsum[i];
        float* op = g_attn + (long)(q0 + ty * 4 + i) * (NH_ * HD_) + h * HD_ + tx * 8;
        float4 o0, o1;
        o0.x = O[i][0]*inv; o0.y = O[i][1]*inv; o0.z = O[i][2]*inv; o0.w = O[i][3]*inv;
        o1.x = O[i][4]*inv; o1.y = O[i][5]*inv; o1.z = O[i][6]*inv; o1.w = O[i][7]*inv;
        *(float4*)op       = o0;
        *(float4*)(op + 4) = o1;
    }
}

// ===================== launch =================================================
static inline void split(const float* x, __nv_bfloat16* hi, __nv_bfloat16* lo, long n)
{
    int n4 = (int)(n / 4);
    split_bf16<<<(n4 + 255) / 256, 256>>>((const float4*)x,
                                          (__nv_bfloat162*)hi, (__nv_bfloat162*)lo, n4);
}

extern "C" void kernel_launch(void* const* d_in, const int* in_sizes, int n_in,
                              void* d_out, int out_size)
{
    const float* hidden  = (const float*)d_in[0];
    const float* context = (const float*)d_in[1];
    const float* Wq  = (const float*)d_in[3];
    const float* Wk  = (const float*)d_in[4];
    const float* Wv  = (const float*)d_in[5];
    const float* Wo  = (const float*)d_in[6];
    const float* Wkc = (const float*)d_in[7];
    const float* Wvc = (const float*)d_in[8];
    const float* qnw = (const float*)d_in[9];
    const float* knw = (const float*)d_in[10];

    float *Qp, *Ktp, *Kfp, *Vfp, *Ap;
    cudaGetSymbolAddress((void**)&Qp,  g_Q);
    cudaGetSymbolAddress((void**)&Ktp, g_Ktmp);
    cudaGetSymbolAddress((void**)&Kfp, g_Kfull);
    cudaGetSymbolAddress((void**)&Vfp, g_Vfull);
    cudaGetSymbolAddress((void**)&Ap,  g_attn);

    __nv_bfloat16 *hid_h, *hid_l, *ctx_h, *ctx_l, *att_h, *att_l;
    __nv_bfloat16 *wq_h, *wq_l, *wo_h, *wo_l, *wk_h, *wk_l, *wv_h, *wv_l;
    __nv_bfloat16 *wkc_h, *wkc_l, *wvc_h, *wvc_l;
    cudaGetSymbolAddress((void**)&hid_h, g_hid_hi); cudaGetSymbolAddress((void**)&hid_l, g_hid_lo);
    cudaGetSymbolAddress((void**)&ctx_h, g_ctx_hi); cudaGetSymbolAddress((void**)&ctx_l, g_ctx_lo);
    cudaGetSymbolAddress((void**)&att_h, g_att_hi); cudaGetSymbolAddress((void**)&att_l, g_att_lo);
    cudaGetSymbolAddress((void**)&wq_h,  g_wq_hi);  cudaGetSymbolAddress((void**)&wq_l,  g_wq_lo);
    cudaGetSymbolAddress((void**)&wo_h,  g_wo_hi);  cudaGetSymbolAddress((void**)&wo_l,  g_wo_lo);
    cudaGetSymbolAddress((void**)&wk_h,  g_wk_hi);  cudaGetSymbolAddress((void**)&wk_l,  g_wk_lo);
    cudaGetSymbolAddress((void**)&wv_h,  g_wv_hi);  cudaGetSymbolAddress((void**)&wv_l,  g_wv_lo);
    cudaGetSymbolAddress((void**)&wkc_h, g_wkc_hi); cudaGetSymbolAddress((void**)&wkc_l, g_wkc_lo);
    cudaGetSymbolAddress((void**)&wvc_h, g_wvc_hi); cudaGetSymbolAddress((void**)&wvc_l, g_wvc_lo);

    // fp32 -> bf16 hi/lo splits
    split(hidden,  hid_h, hid_l, (long)S_ * HID_);
    split(context, ctx_h, ctx_l, (long)L_ * HID_);
    split(Wq,  wq_h,  wq_l,  (long)NH_ * HD_ * HID_);
    split(Wk,  wk_h,  wk_l,  (long)KVH_ * HD_ * HID_);
    split(Wv,  wv_h,  wv_l,  (long)KVH_ * HD_ * HID_);
    split(Wkc, wkc_h, wkc_l, (long)KVH_ * HD_ * HID_);
    split(Wvc, wvc_h, wvc_l, (long)KVH_ * HD_ * HID_);
    split(Wo,  wo_h,  wo_l,  (long)HID_ * NH_ * HD_);

    cudaFuncSetAttribute(gemm_mma, cudaFuncAttributeMaxDynamicSharedMemorySize, G_SMEM);

    const long hstride = (long)T_ * HD_;

    // projections on tensor cores (mma.sync bf16x3)
    gemm_mma<<<dim3(HID_ / 128, S_ / 128), 256, G_SMEM>>>(hid_h, hid_l, wq_h, wq_l, Qp,  HID_, HID_,       0, 0);
    gemm_mma<<<dim3(KVH_ * HD_ / 128, S_ / 128), 256, G_SMEM>>>(hid_h, hid_l, wk_h, wk_l, Ktp, HID_, KVH_ * HD_, 0, 0);
    gemm_mma<<<dim3(KVH_ * HD_ / 128, S_ / 128), 256, G_SMEM>>>(hid_h, hid_l, wv_h, wv_l, Vfp, HID_, KVH_ * HD_, hstride, L_);
    gemm_mma<<<dim3(KVH_ * HD_ / 128, L_ / 128), 256, G_SMEM>>>(ctx_h, ctx_l, wkc_h, wkc_l, Kfp, HID_, KVH_ * HD_, hstride, 0);
    gemm_mma<<<dim3(KVH_ * HD_ / 128, L_ / 128), 256, G_SMEM>>>(ctx_h, ctx_l, wvc_h, wvc_l, Vfp, HID_, KVH_ * HD_, hstride, 0);

    // rmsnorm + rope
    normrope_kernel<<<dim3(S_, NH_ + KVH_), 128>>>(qnw, knw);

    // attention (fp32 SIMT this round)
    cudaFuncSetAttribute(attn_kernel, cudaFuncAttributeMaxDynamicSharedMemorySize, ASMEM);
    attn_kernel<<<dim3(S_ / ABM, NH_), 256, ASMEM>>>();

    // output projection on tensor cores
    split(Ap, att_h, att_l, (long)S_ * HID_);
    gemm_mma<<<dim3(HID_ / 128, S_ / 128), 256, G_SMEM>>>(att_h, att_l, wo_h, wo_l, (float*)d_out, HID_, HID_, 0, 0);
}